// round 8
// baseline (speedup 1.0000x reference)
#include <cuda_runtime.h>

#define NN 100000
#define FD 32

// Scratch (static device globals — no allocation in kernel_launch)
__device__ float g_msgA[NN * FD];   // layer-0 messages
__device__ float g_msgB[NN * FD];   // layer-1 messages
__device__ int   g_csr[2000000];    // CSR src indices (E <= 1.6M, headroom)
__device__ int   g_row[NN];         // CSR row starts
__device__ int   g_cur[NN];         // fill cursors
__device__ int   g_cnt[NN];         // in-degree (no self-loop)
__device__ float g_dinv[NN];
__device__ int   g_total;

__global__ void k_zero() {
    int i = blockIdx.x * blockDim.x + threadIdx.x;
    if (i < NN) g_cnt[i] = 0;
    if (i == 0) g_total = 0;
}

__global__ void k_count(const int* __restrict__ dst, int E) {
    int t = blockIdx.x * blockDim.x + threadIdx.x;
    int e = t * 4;
    if (e + 3 < E) {
        int4 d = *reinterpret_cast<const int4*>(dst + e);
        atomicAdd(&g_cnt[d.x], 1);
        atomicAdd(&g_cnt[d.y], 1);
        atomicAdd(&g_cnt[d.z], 1);
        atomicAdd(&g_cnt[d.w], 1);
    } else {
        for (int i = e; i < E; i++) atomicAdd(&g_cnt[dst[i]], 1);
    }
}

__global__ void k_dinv() {
    int i = blockIdx.x * blockDim.x + threadIdx.x;
    if (i < NN) g_dinv[i] = rsqrtf((float)(g_cnt[i] + 1));  // +1 self-loop
}

// Per-block exclusive scan + one atomicAdd for the block base.
// Block bases are assignment-order-dependent but each node still gets a
// private contiguous range of length cnt[i] -> gather stays correct.
__global__ __launch_bounds__(256) void k_alloc() {
    __shared__ int sh[256];
    __shared__ int base;
    int tid = threadIdx.x;
    int i = blockIdx.x * 256 + tid;
    int c = (i < NN) ? g_cnt[i] : 0;
    sh[tid] = c;
    __syncthreads();
    #pragma unroll
    for (int off = 1; off < 256; off <<= 1) {
        int t = (tid >= off) ? sh[tid - off] : 0;
        __syncthreads();
        sh[tid] += t;
        __syncthreads();
    }
    if (tid == 255) base = atomicAdd(&g_total, sh[255]);
    __syncthreads();
    if (i < NN) {
        int start = base + sh[tid] - c;
        g_row[i] = start;
        g_cur[i] = start;
    }
}

__global__ void k_fill(const int* __restrict__ src,
                       const int* __restrict__ dst, int E) {
    int e = blockIdx.x * blockDim.x + threadIdx.x;
    if (e >= E) return;
    int p = atomicAdd(&g_cur[dst[e]], 1);
    g_csr[p] = src[e];
}

// msg0 = dinv * x  (GCN linearity: W0 applied after aggregation)
__global__ void k_scale0(const float* __restrict__ x) {
    int g = blockIdx.x * blockDim.x + threadIdx.x;   // one float4 per thread
    if (g >= NN * FD / 4) return;
    int node = g >> 3;
    float dv = g_dinv[node];
    float4 v = *reinterpret_cast<const float4*>(x + (size_t)g * 4);
    v.x *= dv; v.y *= dv; v.z *= dv; v.w *= dv;
    *reinterpret_cast<float4*>(g_msgA + (size_t)g * 4) = v;
}

// Gather + fused GEMV: one warp per node, lane = feature.
//   acc = msgA[self] + sum_in msgA[src]   (register accumulation, no atomics)
//   ph = dinv*acc; h1 = relu(ph@W0+b0); msgB = dinv*h1
__global__ __launch_bounds__(256) void k_gmid(const float* __restrict__ W0,
                                              const float* __restrict__ b0) {
    __shared__ float Ws[FD * FD];
    __shared__ float s_row[8][FD];
    int tid = threadIdx.x;
    int lane = tid & 31;
    int wb = tid >> 5;
    #pragma unroll
    for (int i = tid; i < FD * FD; i += 256) Ws[i] = W0[i];
    __syncthreads();

    float Wc[FD];
    #pragma unroll
    for (int k = 0; k < FD; k++) Wc[k] = Ws[k * FD + lane];
    float bl = b0[lane];

    int node = blockIdx.x * 8 + wb;          // grid = NN/8 exactly
    int start = g_row[node];
    int d = g_cnt[node];
    float dv = g_dinv[node];

    float acc = g_msgA[(size_t)node * FD + lane];   // self-loop term
    int i = 0;
    for (; i + 4 <= d; i += 4) {                     // MLP=4 index+gather batch
        int s0 = __ldg(&g_csr[start + i + 0]);
        int s1 = __ldg(&g_csr[start + i + 1]);
        int s2 = __ldg(&g_csr[start + i + 2]);
        int s3 = __ldg(&g_csr[start + i + 3]);
        float a0 = g_msgA[(size_t)s0 * FD + lane];
        float a1 = g_msgA[(size_t)s1 * FD + lane];
        float a2 = g_msgA[(size_t)s2 * FD + lane];
        float a3 = g_msgA[(size_t)s3 * FD + lane];
        acc += (a0 + a1) + (a2 + a3);
    }
    for (; i < d; i++) {
        int s = __ldg(&g_csr[start + i]);
        acc += g_msgA[(size_t)s * FD + lane];
    }

    float ph = dv * acc;
    s_row[wb][lane] = ph;
    __syncwarp();
    const float4* r = reinterpret_cast<const float4*>(s_row[wb]);
    float o = 0.0f;
    #pragma unroll
    for (int j = 0; j < FD / 4; j++) {
        float4 t4 = r[j];
        o = fmaf(t4.x, Wc[4 * j + 0], o);
        o = fmaf(t4.y, Wc[4 * j + 1], o);
        o = fmaf(t4.z, Wc[4 * j + 2], o);
        o = fmaf(t4.w, Wc[4 * j + 3], o);
    }
    __syncwarp();
    g_msgB[(size_t)node * FD + lane] = dv * fmaxf(o + bl, 0.0f);
}

// Gather + fused double GEMV:
//   acc = msgB[self] + sum; ph = dinv*acc; h2 = relu(ph@W1+b1); out = h2@Wf+bf
__global__ __launch_bounds__(256) void k_gfinal(const float* __restrict__ W1,
                                                const float* __restrict__ b1,
                                                const float* __restrict__ Wf,
                                                const float* __restrict__ bf,
                                                float* __restrict__ out) {
    __shared__ float Ws1[FD * FD];
    __shared__ float Wsf[FD * FD];
    __shared__ float s_row[8][FD];
    int tid = threadIdx.x;
    int lane = tid & 31;
    int wb = tid >> 5;
    #pragma unroll
    for (int i = tid; i < FD * FD; i += 256) { Ws1[i] = W1[i]; Wsf[i] = Wf[i]; }
    __syncthreads();

    float Wc1[FD], Wcf[FD];
    #pragma unroll
    for (int k = 0; k < FD; k++) { Wc1[k] = Ws1[k * FD + lane]; Wcf[k] = Wsf[k * FD + lane]; }
    float b1l = b1[lane];
    float bfl = bf[lane];

    int node = blockIdx.x * 8 + wb;
    int start = g_row[node];
    int d = g_cnt[node];
    float dv = g_dinv[node];

    float acc = g_msgB[(size_t)node * FD + lane];
    int i = 0;
    for (; i + 4 <= d; i += 4) {
        int s0 = __ldg(&g_csr[start + i + 0]);
        int s1 = __ldg(&g_csr[start + i + 1]);
        int s2 = __ldg(&g_csr[start + i + 2]);
        int s3 = __ldg(&g_csr[start + i + 3]);
        float a0 = g_msgB[(size_t)s0 * FD + lane];
        float a1 = g_msgB[(size_t)s1 * FD + lane];
        float a2 = g_msgB[(size_t)s2 * FD + lane];
        float a3 = g_msgB[(size_t)s3 * FD + lane];
        acc += (a0 + a1) + (a2 + a3);
    }
    for (; i < d; i++) {
        int s = __ldg(&g_csr[start + i]);
        acc += g_msgB[(size_t)s * FD + lane];
    }

    float ph = dv * acc;
    s_row[wb][lane] = ph;
    __syncwarp();
    const float4* r = reinterpret_cast<const float4*>(s_row[wb]);
    float o1 = 0.0f;
    #pragma unroll
    for (int j = 0; j < FD / 4; j++) {
        float4 t4 = r[j];
        o1 = fmaf(t4.x, Wc1[4 * j + 0], o1);
        o1 = fmaf(t4.y, Wc1[4 * j + 1], o1);
        o1 = fmaf(t4.z, Wc1[4 * j + 2], o1);
        o1 = fmaf(t4.w, Wc1[4 * j + 3], o1);
    }
    __syncwarp();
    float h2 = fmaxf(o1 + b1l, 0.0f);
    s_row[wb][lane] = h2;
    __syncwarp();
    float o2 = bfl;
    #pragma unroll
    for (int j = 0; j < FD / 4; j++) {
        float4 t4 = r[j];
        o2 = fmaf(t4.x, Wcf[4 * j + 0], o2);
        o2 = fmaf(t4.y, Wcf[4 * j + 1], o2);
        o2 = fmaf(t4.z, Wcf[4 * j + 2], o2);
        o2 = fmaf(t4.w, Wcf[4 * j + 3], o2);
    }
    __syncwarp();
    out[(size_t)node * FD + lane] = o2;
}

extern "C" void kernel_launch(void* const* d_in, const int* in_sizes, int n_in,
                              void* d_out, int out_size) {
    const float* x   = (const float*)d_in[0];
    const int*   ei  = (const int*)d_in[1];   // JAX x64 disabled -> int32
    const float* W0  = (const float*)d_in[2];
    const float* b0  = (const float*)d_in[3];
    const float* W1  = (const float*)d_in[4];
    const float* b1  = (const float*)d_in[5];
    const float* Wf  = (const float*)d_in[6];
    const float* bf  = (const float*)d_in[7];
    float* out = (float*)d_out;

    int E = in_sizes[1] / 2;          // edge_index is [2, E]
    const int* src = ei;
    const int* dst = ei + E;

    int nb_n  = (NN + 255) / 256;
    int nb_c  = ((E + 3) / 4 + 255) / 256;
    int nb_e  = (E + 255) / 256;
    int nb_s0 = (NN * FD / 4 + 255) / 256;
    int nb_g  = NN / 8;               // one warp per node, 8 warps/block

    // CSR build + normalization
    k_zero<<<nb_n, 256>>>();
    k_count<<<nb_c, 256>>>(dst, E);
    k_dinv<<<nb_n, 256>>>();
    k_alloc<<<nb_n, 256>>>();
    k_fill<<<nb_e, 256>>>(src, dst, E);

    // layer 0 messages
    k_scale0<<<nb_s0, 256>>>(x);

    // layer 0 aggregate + W0/relu fused -> layer 1 messages
    k_gmid<<<nb_g, 256>>>(W0, b0);

    // layer 1 aggregate + W1/relu + Wf fused -> output
    k_gfinal<<<nb_g, 256>>>(W1, b1, Wf, bf, out);
}

// round 9
// speedup vs baseline: 1.7743x; 1.7743x over previous
#include <cuda_runtime.h>

#define NN 100000
#define FD 32
#define NPW 8
#define EPT 4   // edges per scatter thread

// Scratch (static device globals — no allocation in kernel_launch)
__device__ float g_scaled[NN * FD];  // messages (fp32), gather side
__device__ float g_agg[NN * FD];     // accumulator, seeded with self-loop
__device__ float g_dinv[NN];
__device__ int   g_deg[NN];

__global__ void k_zero() {
    int i = blockIdx.x * blockDim.x + threadIdx.x;
    if (i < NN) g_deg[i] = 1;  // self-loop contributes 1
}

__global__ void k_count(const int* __restrict__ dst, int E) {
    int t = blockIdx.x * blockDim.x + threadIdx.x;
    int e = t * 4;
    if (e + 3 < E) {
        int4 d = *reinterpret_cast<const int4*>(dst + e);
        atomicAdd(&g_deg[d.x], 1);
        atomicAdd(&g_deg[d.y], 1);
        atomicAdd(&g_deg[d.z], 1);
        atomicAdd(&g_deg[d.w], 1);
    } else {
        for (int i = e; i < E; i++) atomicAdd(&g_deg[dst[i]], 1);
    }
}

// s0 = dinv * x; seeds accumulator (self-loop) and computes dinv inline.
__global__ void k_scale0(const float* __restrict__ x) {
    int g = blockIdx.x * blockDim.x + threadIdx.x;   // one float4 per thread
    if (g >= NN * FD / 4) return;
    int node = g >> 3;
    float dv = rsqrtf((float)g_deg[node]);           // redundant per 8 threads, cheap MUFU
    if ((g & 7) == 0) g_dinv[node] = dv;
    float4 v = *reinterpret_cast<const float4*>(x + (size_t)g * 4);
    v.x *= dv; v.y *= dv; v.z *= dv; v.w *= dv;
    *reinterpret_cast<float4*>(g_scaled + (size_t)g * 4) = v;
    *reinterpret_cast<float4*>(g_agg    + (size_t)g * 4) = v;
}

// Scatter: 8 lanes per edge-slot, EPT edges per thread (batched loads, MLP=EPT).
// Each (lane, edge) does one float4 gather + one red.v4.f32. No converts.
__global__ __launch_bounds__(256) void k_scatter(const int* __restrict__ src,
                                                 const int* __restrict__ dst,
                                                 int E) {
    long long t = (long long)blockIdx.x * 256 + threadIdx.x;
    int e0 = (int)(t >> 3) * EPT;
    if (e0 >= E) return;
    int q = ((int)t & 7) << 2;   // feature offset 0,4,...,28

    int s[EPT], d[EPT];
    #pragma unroll
    for (int k = 0; k < EPT; k++) {
        s[k] = src[e0 + k];      // E % EPT == 0 in practice; guarded below anyway
        d[k] = dst[e0 + k];
    }
    float4 v[EPT];
    #pragma unroll
    for (int k = 0; k < EPT; k++)
        v[k] = *reinterpret_cast<const float4*>(&g_scaled[(size_t)s[k] * FD + q]);

    #pragma unroll
    for (int k = 0; k < EPT; k++) {
        float* a = &g_agg[(size_t)d[k] * FD + q];
        asm volatile("red.global.add.v4.f32 [%0], {%1, %2, %3, %4};"
                     :: "l"(a), "f"(v[k].x), "f"(v[k].y), "f"(v[k].z), "f"(v[k].w)
                     : "memory");
    }
}

// Scatter tail for E % EPT != 0 (not hit for E=1.6M, kept for correctness).
__global__ void k_scatter_tail(const int* __restrict__ src,
                               const int* __restrict__ dst,
                               int Ebase, int E) {
    long long t = (long long)blockIdx.x * blockDim.x + threadIdx.x;
    int e = Ebase + (int)(t >> 3);
    if (e >= E) return;
    int q = ((int)t & 7) << 2;
    int s = src[e];
    int d = dst[e];
    const float4 v = *reinterpret_cast<const float4*>(&g_scaled[(size_t)s * FD + q]);
    float* a = &g_agg[(size_t)d * FD + q];
    asm volatile("red.global.add.v4.f32 [%0], {%1, %2, %3, %4};"
                 :: "l"(a), "f"(v.x), "f"(v.y), "f"(v.z), "f"(v.w)
                 : "memory");
}

// Mid: ph = dinv*agg0; h1 = relu(ph @ W0 + b0); s1 = dinv*h1.
__global__ __launch_bounds__(256) void k_mid(const float* __restrict__ W0,
                                             const float* __restrict__ b0) {
    __shared__ float Ws[FD * FD];
    __shared__ float s_row[8][FD];
    int tid = threadIdx.x;
    int lane = tid & 31;
    int wb = tid >> 5;
    #pragma unroll
    for (int i = tid; i < FD * FD; i += 256) Ws[i] = W0[i];
    __syncthreads();

    float Wc[FD];
    #pragma unroll
    for (int k = 0; k < FD; k++) Wc[k] = Ws[k * FD + lane];
    float bl = b0[lane];

    int base = (blockIdx.x * 8 + wb) * NPW;
    if (base >= NN) return;

    float v[NPW], dvv[NPW];
    #pragma unroll
    for (int u = 0; u < NPW; u++) {                  // batched loads, MLP=8
        v[u]   = g_agg[(size_t)(base + u) * FD + lane];
        dvv[u] = __ldg(&g_dinv[base + u]);
    }

    #pragma unroll
    for (int u = 0; u < NPW; u++) {
        int node = base + u;
        s_row[wb][lane] = dvv[u] * v[u];
        __syncwarp();
        const float4* r = reinterpret_cast<const float4*>(s_row[wb]);
        float acc = 0.0f;
        #pragma unroll
        for (int j = 0; j < FD / 4; j++) {
            float4 t4 = r[j];                        // broadcast LDS.128
            acc = fmaf(t4.x, Wc[4 * j + 0], acc);
            acc = fmaf(t4.y, Wc[4 * j + 1], acc);
            acc = fmaf(t4.z, Wc[4 * j + 2], acc);
            acc = fmaf(t4.w, Wc[4 * j + 3], acc);
        }
        __syncwarp();
        float s1 = dvv[u] * fmaxf(acc + bl, 0.0f);
        g_scaled[(size_t)node * FD + lane] = s1;
        g_agg[(size_t)node * FD + lane]    = s1;
    }
}

// Final: ph = dinv*agg1; h2 = relu(ph @ W1 + b1); out = h2 @ Wf + bf.
__global__ __launch_bounds__(256) void k_final(const float* __restrict__ W1,
                                               const float* __restrict__ b1,
                                               const float* __restrict__ Wf,
                                               const float* __restrict__ bf,
                                               float* __restrict__ out) {
    __shared__ float Ws1[FD * FD];
    __shared__ float Wsf[FD * FD];
    __shared__ float s_row[8][FD];
    int tid = threadIdx.x;
    int lane = tid & 31;
    int wb = tid >> 5;
    #pragma unroll
    for (int i = tid; i < FD * FD; i += 256) { Ws1[i] = W1[i]; Wsf[i] = Wf[i]; }
    __syncthreads();

    float Wc1[FD], Wcf[FD];
    #pragma unroll
    for (int k = 0; k < FD; k++) { Wc1[k] = Ws1[k * FD + lane]; Wcf[k] = Wsf[k * FD + lane]; }
    float b1l = b1[lane];
    float bfl = bf[lane];

    int base = (blockIdx.x * 8 + wb) * NPW;
    if (base >= NN) return;

    float v[NPW], dvv[NPW];
    #pragma unroll
    for (int u = 0; u < NPW; u++) {
        v[u]   = g_agg[(size_t)(base + u) * FD + lane];
        dvv[u] = __ldg(&g_dinv[base + u]);
    }

    #pragma unroll
    for (int u = 0; u < NPW; u++) {
        int node = base + u;
        s_row[wb][lane] = dvv[u] * v[u];
        __syncwarp();
        const float4* r = reinterpret_cast<const float4*>(s_row[wb]);
        float o1 = 0.0f;
        #pragma unroll
        for (int j = 0; j < FD / 4; j++) {
            float4 t4 = r[j];
            o1 = fmaf(t4.x, Wc1[4 * j + 0], o1);
            o1 = fmaf(t4.y, Wc1[4 * j + 1], o1);
            o1 = fmaf(t4.z, Wc1[4 * j + 2], o1);
            o1 = fmaf(t4.w, Wc1[4 * j + 3], o1);
        }
        __syncwarp();
        float h2 = fmaxf(o1 + b1l, 0.0f);
        s_row[wb][lane] = h2;
        __syncwarp();
        float o2 = bfl;
        #pragma unroll
        for (int j = 0; j < FD / 4; j++) {
            float4 t4 = r[j];
            o2 = fmaf(t4.x, Wcf[4 * j + 0], o2);
            o2 = fmaf(t4.y, Wcf[4 * j + 1], o2);
            o2 = fmaf(t4.z, Wcf[4 * j + 2], o2);
            o2 = fmaf(t4.w, Wcf[4 * j + 3], o2);
        }
        __syncwarp();
        out[(size_t)node * FD + lane] = o2;
    }
}

extern "C" void kernel_launch(void* const* d_in, const int* in_sizes, int n_in,
                              void* d_out, int out_size) {
    const float* x   = (const float*)d_in[0];
    const int*   ei  = (const int*)d_in[1];   // JAX x64 disabled -> int32
    const float* W0  = (const float*)d_in[2];
    const float* b0  = (const float*)d_in[3];
    const float* W1  = (const float*)d_in[4];
    const float* b1  = (const float*)d_in[5];
    const float* Wf  = (const float*)d_in[6];
    const float* bf  = (const float*)d_in[7];
    float* out = (float*)d_out;

    int E = in_sizes[1] / 2;          // edge_index is [2, E]
    const int* src = ei;
    const int* dst = ei + E;

    int Emain = (E / EPT) * EPT;
    int Etail = E - Emain;

    int nb_n  = (NN + 255) / 256;
    int nb_c  = ((E + 3) / 4 + 255) / 256;
    int nb_s0 = (NN * FD / 4 + 255) / 256;
    int warps = (NN + NPW - 1) / NPW;            // 12500
    int nb_x  = (warps + 7) / 8;                 // 1563
    long long sthreads = (long long)(Emain / EPT) * 8;
    int nb_s  = (int)((sthreads + 255) / 256);
    int nb_st = Etail ? ((Etail * 8 + 255) / 256) : 0;

    // degree + normalization (dinv fused into scale0)
    k_zero<<<nb_n, 256>>>();
    k_count<<<nb_c, 256>>>(dst, E);

    // layer 0: scale only (W0 applied after aggregation)
    k_scale0<<<nb_s0, 256>>>(x);
    k_scatter<<<nb_s, 256>>>(src, dst, Emain);
    if (nb_st) k_scatter_tail<<<nb_st, 256>>>(src, dst, Emain, E);

    // mid: apply W0 + relu, produce layer-1 messages
    k_mid<<<nb_x, 256>>>(W0, b0);
    k_scatter<<<nb_s, 256>>>(src, dst, Emain);
    if (nb_st) k_scatter_tail<<<nb_st, 256>>>(src, dst, Emain, E);

    // final: apply W1 + relu, then Wf + bf
    k_final<<<nb_x, 256>>>(W1, b1, Wf, bf, out);
}